// round 4
// baseline (speedup 1.0000x reference)
#include <cuda_runtime.h>

// WindowAttention3D fused kernel: one CTA per window.
//   B=2048 windows, N=98 tokens, C=128 channels, H=4 heads, hd=32.
// Everything for a window lives in SMEM:
//   qkv buffer [98][388]  (q|k|v, pitch-padded; q slot later reused for attn output)
//   region A   [12936 f]  (x tile [98][132] -> scores [112][112] -> proj_w chunk [64][132])
//   wch        [48][132]  (qkv_w chunk staging)
// Total dynamic smem = 229184 B.

#define NTOK 98
#define CDIM 128
#define NHEADS 4
#define HD 32
#define QP 388      // qkv row pitch (floats)
#define XP 132      // x tile row pitch
#define SP 112      // score tile pitch (rows & cols padded to 112 = 16*7)
#define WP 132      // weight chunk row pitch
#define CHUNK 48    // qkv_w columns per staging chunk
#define NTHREADS 256
#define SMEM_FLOATS (NTOK*QP + 12936 + CHUNK*WP)

__global__ __launch_bounds__(NTHREADS, 1)
void wa3d_kernel(const float* __restrict__ x,
                 const float* __restrict__ mask,
                 const float* __restrict__ qkv_w,
                 const float* __restrict__ qkv_b,
                 const float* __restrict__ rel,
                 const float* __restrict__ proj_w,
                 const float* __restrict__ proj_b,
                 float* __restrict__ out,
                 int Lmask)
{
    extern __shared__ float sm[];
    float* qkv = sm;                 // NTOK*QP = 38024 floats
    float* A   = sm + NTOK*QP;       // 12936 floats (union region)
    float* wch = A + 12936;          // CHUNK*WP = 6336 floats

    const int tid = threadIdx.x;
    const int b = blockIdx.x;
    const float scale = 0.17677669529663688f;   // 32^-0.5

    // ---------------- load x tile: A = xs[98][132] ----------------
    {
        const float4* xb = (const float4*)(x + (size_t)b * NTOK * CDIM);
        for (int f = tid; f < NTOK*CDIM/4; f += NTHREADS) {
            int row = f >> 5;          // 32 float4 per row
            int c4  = f & 31;
            float4 v = xb[f];
            *(float4*)&A[row*XP + c4*4] = v;
        }
    }
    __syncthreads();

    // ---------------- QKV projection: qkv[i][col] = x[i]·w[col] + b ----------------
    {
        const int ty = tid >> 4, tx = tid & 15;
        int irow[7];
        #pragma unroll
        for (int r = 0; r < 7; r++) irow[r] = min(ty + 16*r, NTOK-1) * XP;

        for (int ch = 0; ch < 8; ch++) {
            const int c0 = ch * CHUNK;
            for (int f = tid; f < CHUNK*CDIM/4; f += NTHREADS) {
                int row = f >> 5, c4 = f & 31;
                float4 v = ((const float4*)(qkv_w + (size_t)(c0 + row)*CDIM))[c4];
                *(float4*)&wch[row*WP + c4*4] = v;
            }
            __syncthreads();

            float acc[7][3];
            #pragma unroll
            for (int r = 0; r < 7; r++)
                #pragma unroll
                for (int c = 0; c < 3; c++) acc[r][c] = 0.f;

            #pragma unroll 4
            for (int k4 = 0; k4 < 32; k4++) {
                float4 wv[3];
                #pragma unroll
                for (int c = 0; c < 3; c++)
                    wv[c] = *(const float4*)&wch[(tx + 16*c)*WP + k4*4];
                #pragma unroll
                for (int r = 0; r < 7; r++) {
                    float4 xv = *(const float4*)&A[irow[r] + k4*4];
                    #pragma unroll
                    for (int c = 0; c < 3; c++)
                        acc[r][c] += xv.x*wv[c].x + xv.y*wv[c].y
                                   + xv.z*wv[c].z + xv.w*wv[c].w;
                }
            }
            #pragma unroll
            for (int r = 0; r < 7; r++) {
                int i = ty + 16*r;
                if (i < NTOK) {
                    #pragma unroll
                    for (int c = 0; c < 3; c++) {
                        int col = c0 + tx + 16*c;
                        float v = acc[r][c] + qkv_b[col];
                        if (col < CDIM) v *= scale;          // q gets the scale
                        qkv[i*QP + col] = v;
                    }
                }
            }
            __syncthreads();
        }
    }

    // ---------------- attention: per-head scores -> softmax -> P@V ----------------
    float* s = A;                                           // s[112][112]
    const float* maskb = mask + (size_t)(b % Lmask) * NTOK * NTOK;

    for (int h = 0; h < NHEADS; h++) {
        const float* relh = rel + h * 507;

        // --- scores: s[i][j] = q_h[i]·k_h[j] + bias + mask ---
        {
            const int ty = tid >> 4, tx = tid & 15;
            int iq[7], jk[7];
            #pragma unroll
            for (int r = 0; r < 7; r++) iq[r] = min(ty + 16*r, NTOK-1);
            #pragma unroll
            for (int c = 0; c < 7; c++) jk[c] = min(tx + 16*c, NTOK-1);

            float acc[7][7];
            #pragma unroll
            for (int r = 0; r < 7; r++)
                #pragma unroll
                for (int c = 0; c < 7; c++) acc[r][c] = 0.f;

            const int qb = h*HD, kb = CDIM + h*HD;
            #pragma unroll
            for (int d4 = 0; d4 < 8; d4++) {
                float4 kv[7];
                #pragma unroll
                for (int c = 0; c < 7; c++)
                    kv[c] = *(const float4*)&qkv[jk[c]*QP + kb + d4*4];
                #pragma unroll
                for (int r = 0; r < 7; r++) {
                    float4 qv = *(const float4*)&qkv[iq[r]*QP + qb + d4*4];
                    #pragma unroll
                    for (int c = 0; c < 7; c++)
                        acc[r][c] += qv.x*kv[c].x + qv.y*kv[c].y
                                   + qv.z*kv[c].z + qv.w*kv[c].w;
                }
            }
            // relative-position bias (computed from constant window geometry 2x7x7)
            #pragma unroll
            for (int r = 0; r < 7; r++) {
                int i  = iq[r];
                int ti = i/49, hi2 = (i/7)%7, wi = i%7;
                #pragma unroll
                for (int c = 0; c < 7; c++) {
                    int j  = jk[c];
                    int tj = j/49, hj = (j/7)%7, wj = j%7;
                    int idx = (ti - tj + 1)*169 + (hi2 - hj + 6)*13 + (wi - wj + 6);
                    float v = acc[r][c] + __ldg(&relh[idx]) + __ldg(&maskb[i*NTOK + j]);
                    s[(ty + 16*r)*SP + (tx + 16*c)] = v;
                }
            }
        }
        __syncthreads();

        // --- softmax over j (one warp per row) ---
        {
            const int warp = tid >> 5, lane = tid & 31;
            for (int row = warp; row < NTOK; row += 8) {
                float v0 = (lane      < NTOK) ? s[row*SP + lane     ] : -1e30f;
                float v1 = (lane + 32 < NTOK) ? s[row*SP + lane + 32] : -1e30f;
                float v2 = (lane + 64 < NTOK) ? s[row*SP + lane + 64] : -1e30f;
                float v3 = (lane + 96 < NTOK) ? s[row*SP + lane + 96] : -1e30f;
                float m = fmaxf(fmaxf(v0, v1), fmaxf(v2, v3));
                #pragma unroll
                for (int o = 16; o > 0; o >>= 1)
                    m = fmaxf(m, __shfl_xor_sync(0xffffffffu, m, o));
                v0 = __expf(v0 - m); v1 = __expf(v1 - m);
                v2 = __expf(v2 - m); v3 = __expf(v3 - m);
                float sum = v0 + v1 + v2 + v3;
                #pragma unroll
                for (int o = 16; o > 0; o >>= 1)
                    sum += __shfl_xor_sync(0xffffffffu, sum, o);
                float inv = 1.0f / sum;
                if (lane      < NTOK) s[row*SP + lane     ] = v0*inv;
                if (lane + 32 < NTOK) s[row*SP + lane + 32] = v1*inv;
                if (lane + 64 < NTOK) s[row*SP + lane + 64] = v2*inv;
                if (lane + 96 < NTOK) s[row*SP + lane + 96] = v3*inv;
            }
        }
        __syncthreads();

        // --- o_h = P @ v_h, written over the (now dead) q_h slot ---
        {
            const int tx = tid & 7, ty = tid >> 3;          // tx: 8 col groups, ty: 32 row groups
            int ir[4];
            #pragma unroll
            for (int r = 0; r < 4; r++) ir[r] = min(ty + 32*r, SP-1) * SP;
            const int vb = 2*CDIM + h*HD + tx*4;

            float acc[4][4];
            #pragma unroll
            for (int r = 0; r < 4; r++)
                #pragma unroll
                for (int c = 0; c < 4; c++) acc[r][c] = 0.f;

            #pragma unroll 2
            for (int k = 0; k < NTOK; k++) {
                float4 vv = *(const float4*)&qkv[k*QP + vb];
                #pragma unroll
                for (int r = 0; r < 4; r++) {
                    float sv = s[ir[r] + k];
                    acc[r][0] += sv*vv.x; acc[r][1] += sv*vv.y;
                    acc[r][2] += sv*vv.z; acc[r][3] += sv*vv.w;
                }
            }
            #pragma unroll
            for (int r = 0; r < 4; r++) {
                int i = ty + 32*r;
                if (i < NTOK) {
                    float4 o4 = make_float4(acc[r][0], acc[r][1], acc[r][2], acc[r][3]);
                    *(float4*)&qkv[i*QP + h*HD + tx*4] = o4;
                }
            }
        }
        __syncthreads();
    }

    // ---------------- output projection: out[i][c] = o[i]·proj_w[c] + b[c] ----------------
    {
        const int ty = tid >> 4, tx = tid & 15;
        float* pw = A;                                      // proj_w chunk [64][132]
        int irow[7];
        #pragma unroll
        for (int r = 0; r < 7; r++) irow[r] = min(ty + 16*r, NTOK-1) * QP;

        for (int ch = 0; ch < 2; ch++) {
            const int c0 = ch * 64;
            for (int f = tid; f < 64*CDIM/4; f += NTHREADS) {
                int row = f >> 5, c4 = f & 31;
                float4 v = ((const float4*)(proj_w + (size_t)(c0 + row)*CDIM))[c4];
                *(float4*)&pw[row*WP + c4*4] = v;
            }
            __syncthreads();

            float acc[7][4];
            #pragma unroll
            for (int r = 0; r < 7; r++)
                #pragma unroll
                for (int c = 0; c < 4; c++) acc[r][c] = 0.f;

            #pragma unroll 4
            for (int k4 = 0; k4 < 32; k4++) {
                float4 wv[4];
                #pragma unroll
                for (int c = 0; c < 4; c++)
                    wv[c] = *(const float4*)&pw[(tx + 16*c)*WP + k4*4];
                #pragma unroll
                for (int r = 0; r < 7; r++) {
                    float4 ov = *(const float4*)&qkv[irow[r] + k4*4];
                    #pragma unroll
                    for (int c = 0; c < 4; c++)
                        acc[r][c] += ov.x*wv[c].x + ov.y*wv[c].y
                                   + ov.z*wv[c].z + ov.w*wv[c].w;
                }
            }
            #pragma unroll
            for (int r = 0; r < 7; r++) {
                int i = ty + 16*r;
                if (i < NTOK) {
                    #pragma unroll
                    for (int c = 0; c < 4; c++) {
                        int col = c0 + tx + 16*c;
                        out[(size_t)b*NTOK*CDIM + i*CDIM + col] = acc[r][c] + proj_b[col];
                    }
                }
            }
            __syncthreads();
        }
    }
}

extern "C" void kernel_launch(void* const* d_in, const int* in_sizes, int n_in,
                              void* d_out, int out_size)
{
    const float* x      = (const float*)d_in[0];
    const float* mask   = (const float*)d_in[1];
    const float* qkv_w  = (const float*)d_in[2];
    const float* qkv_b  = (const float*)d_in[3];
    const float* rel    = (const float*)d_in[4];
    const float* proj_w = (const float*)d_in[5];
    const float* proj_b = (const float*)d_in[6];

    const int B = in_sizes[0] / (NTOK * CDIM);          // 2048
    const int L = in_sizes[1] / (NTOK * NTOK);          // 512

    const size_t smem_bytes = (size_t)SMEM_FLOATS * sizeof(float);   // 229184
    cudaFuncSetAttribute(wa3d_kernel,
                         cudaFuncAttributeMaxDynamicSharedMemorySize,
                         (int)smem_bytes);

    wa3d_kernel<<<B, NTHREADS, smem_bytes>>>(x, mask, qkv_w, qkv_b, rel,
                                             proj_w, proj_b, (float*)d_out, L);
}

// round 5
// speedup vs baseline: 1.1243x; 1.1243x over previous
#include <cuda_runtime.h>

// WindowAttention3D fused kernel: one CTA per window.
//   B=2048 windows, N=98 tokens, C=128 channels, H=4 heads, hd=32.
// R4: packed fp32x2 FMA (FFMA2) inner loops + linearized rel-pos index.
// SMEM layout (dynamic, 229184 B):
//   qkv [98][388]  (q|k|v; q slot reused for attn output)
//   A   [12936 f]  (x tile [98][132] -> scores [112][112] -> proj_w chunk [64][132])
//   wch [48][132]  (qkv_w chunk staging)

#define NTOK 98
#define CDIM 128
#define NHEADS 4
#define HD 32
#define QP 388
#define XP 132
#define SP 112
#define WP 132
#define CHUNK 48
#define NTHREADS 256
#define SMEM_FLOATS (NTOK*QP + 12936 + CHUNK*WP)

typedef unsigned long long u64;

// d.lo += a.lo*b.lo ; d.hi += a.hi*b.hi   (one FFMA2 issue slot, 2 fp32 FMAs)
__device__ __forceinline__ void fma2(u64& d, u64 a, u64 b) {
    asm("fma.rn.f32x2 %0, %1, %2, %0;" : "+l"(d) : "l"(a), "l"(b));
}
__device__ __forceinline__ float hsum2(u64 v) {
    float a, b;
    asm("mov.b64 {%0, %1}, %2;" : "=f"(a), "=f"(b) : "l"(v));
    return a + b;
}
__device__ __forceinline__ u64 dup2(float s) {
    u64 r;
    asm("mov.b64 %0, {%1, %1};" : "=l"(r) : "f"(s));
    return r;
}

__global__ __launch_bounds__(NTHREADS, 1)
void wa3d_kernel(const float* __restrict__ x,
                 const float* __restrict__ mask,
                 const float* __restrict__ qkv_w,
                 const float* __restrict__ qkv_b,
                 const float* __restrict__ rel,
                 const float* __restrict__ proj_w,
                 const float* __restrict__ proj_b,
                 float* __restrict__ out,
                 int Lmask)
{
    extern __shared__ float sm[];
    float* qkv = sm;                 // NTOK*QP floats
    float* A   = sm + NTOK*QP;       // 12936 floats (union region)
    float* wch = A + 12936;          // CHUNK*WP floats

    const int tid = threadIdx.x;
    const int b = blockIdx.x;
    const float scale = 0.17677669529663688f;   // 32^-0.5

    // ---------------- load x tile: A = xs[98][132] ----------------
    {
        const float4* xb = (const float4*)(x + (size_t)b * NTOK * CDIM);
        for (int f = tid; f < NTOK*CDIM/4; f += NTHREADS) {
            int row = f >> 5;
            int c4  = f & 31;
            float4 v = xb[f];
            *(float4*)&A[row*XP + c4*4] = v;
        }
    }
    __syncthreads();

    // ---------------- QKV projection: qkv[i][col] = x[i]·w[col] + b ----------------
    {
        const int ty = tid >> 4, tx = tid & 15;
        int irow[7];
        #pragma unroll
        for (int r = 0; r < 7; r++) irow[r] = min(ty + 16*r, NTOK-1) * XP;

        for (int ch = 0; ch < 8; ch++) {
            const int c0 = ch * CHUNK;
            for (int f = tid; f < CHUNK*CDIM/4; f += NTHREADS) {
                int row = f >> 5, c4 = f & 31;
                float4 v = ((const float4*)(qkv_w + (size_t)(c0 + row)*CDIM))[c4];
                *(float4*)&wch[row*WP + c4*4] = v;
            }
            __syncthreads();

            u64 acc[7][3];
            #pragma unroll
            for (int r = 0; r < 7; r++)
                #pragma unroll
                for (int c = 0; c < 3; c++) acc[r][c] = 0ull;

            #pragma unroll 4
            for (int k4 = 0; k4 < 32; k4++) {
                ulonglong2 wv[3];
                #pragma unroll
                for (int c = 0; c < 3; c++)
                    wv[c] = *(const ulonglong2*)&wch[(tx + 16*c)*WP + k4*4];
                #pragma unroll
                for (int r = 0; r < 7; r++) {
                    ulonglong2 xv = *(const ulonglong2*)&A[irow[r] + k4*4];
                    #pragma unroll
                    for (int c = 0; c < 3; c++) {
                        fma2(acc[r][c], xv.x, wv[c].x);
                        fma2(acc[r][c], xv.y, wv[c].y);
                    }
                }
            }
            #pragma unroll
            for (int r = 0; r < 7; r++) {
                int i = ty + 16*r;
                if (i < NTOK) {
                    #pragma unroll
                    for (int c = 0; c < 3; c++) {
                        int col = c0 + tx + 16*c;
                        float v = hsum2(acc[r][c]) + qkv_b[col];
                        if (col < CDIM) v *= scale;          // q gets the scale
                        qkv[i*QP + col] = v;
                    }
                }
            }
            __syncthreads();
        }
    }

    // ---------------- attention: per-head scores -> softmax -> P@V ----------------
    float* s = A;                                           // s[112][112]
    const float* maskb = mask + (size_t)(b % Lmask) * NTOK * NTOK;

    // thread-constant geometry for scores tile (ty/tx mapping: 16x16)
    const int s_ty = tid >> 4, s_tx = tid & 15;
    int iq[7], jk[7], ai[7], bj[7];
    #pragma unroll
    for (int r = 0; r < 7; r++) {
        int i = min(s_ty + 16*r, NTOK-1);
        iq[r] = i;
        ai[r] = (i/49)*169 + ((i/7)%7)*13 + (i%7);
    }
    #pragma unroll
    for (int c = 0; c < 7; c++) {
        int j = min(s_tx + 16*c, NTOK-1);
        jk[c] = j;
        bj[c] = (j/49)*169 + ((j/7)%7)*13 + (j%7);
    }

    for (int h = 0; h < NHEADS; h++) {
        const float* relh = rel + h * 507;

        // --- scores: s[i][j] = q_h[i]·k_h[j] + bias + mask ---
        {
            u64 acc[7][7];
            #pragma unroll
            for (int r = 0; r < 7; r++)
                #pragma unroll
                for (int c = 0; c < 7; c++) acc[r][c] = 0ull;

            const int qb = h*HD, kb = CDIM + h*HD;
            #pragma unroll
            for (int d4 = 0; d4 < 8; d4++) {
                ulonglong2 kv[7];
                #pragma unroll
                for (int c = 0; c < 7; c++)
                    kv[c] = *(const ulonglong2*)&qkv[jk[c]*QP + kb + d4*4];
                #pragma unroll
                for (int r = 0; r < 7; r++) {
                    ulonglong2 qv = *(const ulonglong2*)&qkv[iq[r]*QP + qb + d4*4];
                    #pragma unroll
                    for (int c = 0; c < 7; c++) {
                        fma2(acc[r][c], qv.x, kv[c].x);
                        fma2(acc[r][c], qv.y, kv[c].y);
                    }
                }
            }
            // epilogue: bias + mask; rel idx = ai - bj + 253 (linearized)
            #pragma unroll
            for (int r = 0; r < 7; r++) {
                int i = iq[r];
                #pragma unroll
                for (int c = 0; c < 7; c++) {
                    int idx = ai[r] - bj[c] + 253;
                    float v = hsum2(acc[r][c]) + __ldg(&relh[idx])
                            + __ldg(&maskb[i*NTOK + jk[c]]);
                    s[(s_ty + 16*r)*SP + (s_tx + 16*c)] = v;
                }
            }
        }
        __syncthreads();

        // --- softmax over j (one warp per row) ---
        {
            const int warp = tid >> 5, lane = tid & 31;
            for (int row = warp; row < NTOK; row += 8) {
                float v0 = (lane      < NTOK) ? s[row*SP + lane     ] : -1e30f;
                float v1 = (lane + 32 < NTOK) ? s[row*SP + lane + 32] : -1e30f;
                float v2 = (lane + 64 < NTOK) ? s[row*SP + lane + 64] : -1e30f;
                float v3 = (lane + 96 < NTOK) ? s[row*SP + lane + 96] : -1e30f;
                float m = fmaxf(fmaxf(v0, v1), fmaxf(v2, v3));
                #pragma unroll
                for (int o = 16; o > 0; o >>= 1)
                    m = fmaxf(m, __shfl_xor_sync(0xffffffffu, m, o));
                v0 = __expf(v0 - m); v1 = __expf(v1 - m);
                v2 = __expf(v2 - m); v3 = __expf(v3 - m);
                float sum = v0 + v1 + v2 + v3;
                #pragma unroll
                for (int o = 16; o > 0; o >>= 1)
                    sum += __shfl_xor_sync(0xffffffffu, sum, o);
                float inv = 1.0f / sum;
                if (lane      < NTOK) s[row*SP + lane     ] = v0*inv;
                if (lane + 32 < NTOK) s[row*SP + lane + 32] = v1*inv;
                if (lane + 64 < NTOK) s[row*SP + lane + 64] = v2*inv;
                if (lane + 96 < NTOK) s[row*SP + lane + 96] = v3*inv;
            }
        }
        __syncthreads();

        // --- o_h = P @ v_h, written over the (now dead) q_h slot ---
        {
            const int tx = tid & 7, ty = tid >> 3;
            int ir[4];
            #pragma unroll
            for (int r = 0; r < 4; r++) ir[r] = min(ty + 32*r, SP-1) * SP;
            const int vb = 2*CDIM + h*HD + tx*4;

            u64 acc0[4], acc1[4];                  // cols (x,y) and (z,w)
            #pragma unroll
            for (int r = 0; r < 4; r++) { acc0[r] = 0ull; acc1[r] = 0ull; }

            #pragma unroll 2
            for (int k = 0; k < NTOK; k++) {
                ulonglong2 vv = *(const ulonglong2*)&qkv[k*QP + vb];
                #pragma unroll
                for (int r = 0; r < 4; r++) {
                    u64 sp = dup2(s[ir[r] + k]);
                    fma2(acc0[r], sp, vv.x);
                    fma2(acc1[r], sp, vv.y);
                }
            }
            #pragma unroll
            for (int r = 0; r < 4; r++) {
                int i = ty + 32*r;
                if (i < NTOK) {
                    ulonglong2 o2; o2.x = acc0[r]; o2.y = acc1[r];
                    *(ulonglong2*)&qkv[i*QP + h*HD + tx*4] = o2;
                }
            }
        }
        __syncthreads();
    }

    // ---------------- output projection: out[i][c] = o[i]·proj_w[c] + b[c] ----------------
    {
        const int ty = tid >> 4, tx = tid & 15;
        float* pw = A;                                      // proj_w chunk [64][132]
        int irow[7];
        #pragma unroll
        for (int r = 0; r < 7; r++) irow[r] = min(ty + 16*r, NTOK-1) * QP;

        for (int ch = 0; ch < 2; ch++) {
            const int c0 = ch * 64;
            for (int f = tid; f < 64*CDIM/4; f += NTHREADS) {
                int row = f >> 5, c4 = f & 31;
                float4 v = ((const float4*)(proj_w + (size_t)(c0 + row)*CDIM))[c4];
                *(float4*)&pw[row*WP + c4*4] = v;
            }
            __syncthreads();

            u64 acc[7][4];
            #pragma unroll
            for (int r = 0; r < 7; r++)
                #pragma unroll
                for (int c = 0; c < 4; c++) acc[r][c] = 0ull;

            #pragma unroll 4
            for (int k4 = 0; k4 < 32; k4++) {
                ulonglong2 wv[4];
                #pragma unroll
                for (int c = 0; c < 4; c++)
                    wv[c] = *(const ulonglong2*)&pw[(tx + 16*c)*WP + k4*4];
                #pragma unroll
                for (int r = 0; r < 7; r++) {
                    ulonglong2 ov = *(const ulonglong2*)&qkv[irow[r] + k4*4];
                    #pragma unroll
                    for (int c = 0; c < 4; c++) {
                        fma2(acc[r][c], ov.x, wv[c].x);
                        fma2(acc[r][c], ov.y, wv[c].y);
                    }
                }
            }
            #pragma unroll
            for (int r = 0; r < 7; r++) {
                int i = ty + 16*r;
                if (i < NTOK) {
                    #pragma unroll
                    for (int c = 0; c < 4; c++) {
                        int col = c0 + tx + 16*c;
                        out[(size_t)b*NTOK*CDIM + i*CDIM + col] = hsum2(acc[r][c]) + proj_b[col];
                    }
                }
            }
            __syncthreads();
        }
    }
}

extern "C" void kernel_launch(void* const* d_in, const int* in_sizes, int n_in,
                              void* d_out, int out_size)
{
    const float* x      = (const float*)d_in[0];
    const float* mask   = (const float*)d_in[1];
    const float* qkv_w  = (const float*)d_in[2];
    const float* qkv_b  = (const float*)d_in[3];
    const float* rel    = (const float*)d_in[4];
    const float* proj_w = (const float*)d_in[5];
    const float* proj_b = (const float*)d_in[6];

    const int B = in_sizes[0] / (NTOK * CDIM);          // 2048
    const int L = in_sizes[1] / (NTOK * NTOK);          // 512

    const size_t smem_bytes = (size_t)SMEM_FLOATS * sizeof(float);   // 229184
    cudaFuncSetAttribute(wa3d_kernel,
                         cudaFuncAttributeMaxDynamicSharedMemorySize,
                         (int)smem_bytes);

    wa3d_kernel<<<B, NTHREADS, smem_bytes>>>(x, mask, qkv_w, qkv_b, rel,
                                             proj_w, proj_b, (float*)d_out, L);
}